// round 5
// baseline (speedup 1.0000x reference)
#include <cuda_runtime.h>
#include <cuda_bf16.h>

// DistortionLoss: eff_distloss over B rays of N=128 samples.
//   loss = 0.01 * mean_over_rays[ (1/3)*sum(s*w^2) + 2*sum_i( wm_i*Wexcl_i - w_i*WMexcl_i ) ]
// One warp per ray; float4 coalesced loads; warp shfl scan for exclusive prefix sums;
// deterministic two-stage reduction (no float atomics).

static constexpr int N_SAMPLES      = 128;
static constexpr int WARPS_PER_BLK  = 8;
static constexpr int THREADS        = WARPS_PER_BLK * 32;
static constexpr int MAX_PARTIALS   = 65536;

__device__ float g_partials[MAX_PARTIALS];

__global__ __launch_bounds__(THREADS)
void distloss_main(const float4* __restrict__ w4,
                   const float4* __restrict__ m4,
                   const float4* __restrict__ s4,
                   int B)
{
    const int gwarp = (int)((blockIdx.x * (unsigned)THREADS + threadIdx.x) >> 5);
    const int lane  = threadIdx.x & 31;

    float ray_part = 0.0f;
    if (gwarp < B) {
        // Each ray is 128 floats = 32 float4; lane l owns elements [4l, 4l+4).
        const long idx = (long)gwarp * 32 + lane;
        const float4 wv = __ldg(w4 + idx);
        const float4 mv = __ldg(m4 + idx);
        const float4 sv = __ldg(s4 + idx);

        // uni term: s * w^2
        float uni = sv.x * wv.x * wv.x + sv.y * wv.y * wv.y
                  + sv.z * wv.z * wv.z + sv.w * wv.w * wv.w;

        // per-lane w*m products and lane subtotals
        const float wm0 = wv.x * mv.x, wm1 = wv.y * mv.y;
        const float wm2 = wv.z * mv.z, wm3 = wv.w * mv.w;
        const float wsum  = (wv.x + wv.y) + (wv.z + wv.w);
        const float wmsum = (wm0 + wm1) + (wm2 + wm3);

        // inclusive warp scans of lane subtotals (w and w*m together)
        float wi = wsum, wmi = wmsum;
        #pragma unroll
        for (int d = 1; d < 32; d <<= 1) {
            float tw = __shfl_up_sync(0xffffffffu, wi,  d);
            float tm = __shfl_up_sync(0xffffffffu, wmi, d);
            if (lane >= d) { wi += tw; wmi += tm; }
        }
        // exclusive prefixes at this lane's first element
        float W  = wi  - wsum;
        float WM = wmi - wmsum;

        // bi term: sequential within the lane's 4 elements.
        // Element 0 of the ray naturally contributes 0 (W=WM=0 there).
        float bi;
        bi  = wm0 * W - wv.x * WM;  W += wv.x;  WM += wm0;
        bi += wm1 * W - wv.y * WM;  W += wv.y;  WM += wm1;
        bi += wm2 * W - wv.z * WM;  W += wv.z;  WM += wm2;
        bi += wm3 * W - wv.w * WM;

        ray_part = (1.0f / 3.0f) * uni + 2.0f * bi;
    }

    // warp reduce (ray loss is distributed across lanes)
    #pragma unroll
    for (int d = 16; d; d >>= 1)
        ray_part += __shfl_xor_sync(0xffffffffu, ray_part, d);

    __shared__ float wsums[WARPS_PER_BLK];
    if (lane == 0) wsums[threadIdx.x >> 5] = ray_part;
    __syncthreads();

    if (threadIdx.x == 0) {
        float t = 0.0f;
        #pragma unroll
        for (int i = 0; i < WARPS_PER_BLK; i++) t += wsums[i];
        g_partials[blockIdx.x] = t;
    }
}

__global__ __launch_bounds__(1024)
void distloss_reduce(float* __restrict__ out, int nPartials, int B)
{
    double acc = 0.0;
    for (int i = threadIdx.x; i < nPartials; i += 1024)
        acc += (double)g_partials[i];

    __shared__ double sh[1024];
    sh[threadIdx.x] = acc;
    __syncthreads();
    #pragma unroll
    for (int st = 512; st; st >>= 1) {
        if (threadIdx.x < st) sh[threadIdx.x] += sh[threadIdx.x + st];
        __syncthreads();
    }
    if (threadIdx.x == 0)
        out[0] = (float)(sh[0] * 0.01 / (double)B);
}

extern "C" void kernel_launch(void* const* d_in, const int* in_sizes, int n_in,
                              void* d_out, int out_size)
{
    const float4* w4 = (const float4*)d_in[0];  // weights   [B,128]
    const float4* m4 = (const float4*)d_in[1];  // distances [B,128]
    const float4* s4 = (const float4*)d_in[2];  // intervals [B,128]
    float* out = (float*)d_out;

    const int B = in_sizes[0] / N_SAMPLES;
    const int nBlocks = (B + WARPS_PER_BLK - 1) / WARPS_PER_BLK;  // 32768 for B=262144

    distloss_main<<<nBlocks, THREADS>>>(w4, m4, s4, B);
    distloss_reduce<<<1, 1024>>>(out, nBlocks, B);
}

// round 7
// speedup vs baseline: 1.2631x; 1.2631x over previous
#include <cuda_runtime.h>
#include <cuda_bf16.h>

// DistortionLoss: eff_distloss over B rays of N=128 samples.
//   loss = 0.01 * mean_over_rays[ (1/3)*sum(s*w^2) + 2*sum_i( wm_i*Wexcl_i - w_i*WMexcl_i ) ]
//
// Single fused kernel:
//  - one warp per ray, grid-stride over rays (16 rays/warp at default shape)
//  - float4 coalesced loads, warp shfl scan for exclusive prefix sums
//  - per-block fp32 partial -> last-block-done pattern reduces 2048 partials
//    in double (fixed order => deterministic), writes scalar, resets counter
//    so the kernel is CUDA-graph replayable.

static constexpr int N_SAMPLES     = 128;
static constexpr int THREADS       = 256;
static constexpr int WARPS_PER_BLK = THREADS / 32;
static constexpr int GRID_BLOCKS   = 2048;

__device__ float        g_partials[GRID_BLOCKS];
__device__ unsigned int g_count;   // zero-initialized at module load; self-resets

__global__ __launch_bounds__(THREADS)
void distloss_fused(const float4* __restrict__ w4,
                    const float4* __restrict__ m4,
                    const float4* __restrict__ s4,
                    int B,
                    float* __restrict__ out)
{
    const int lane       = threadIdx.x & 31;
    const int warpInBlk  = threadIdx.x >> 5;
    const int gwarp      = blockIdx.x * WARPS_PER_BLK + warpInBlk;
    const int totalWarps = gridDim.x * WARPS_PER_BLK;

    // Per-lane accumulator of this warp's rays (lane-distributed; reduced once at end).
    float acc = 0.0f;

    for (int ray = gwarp; ray < B; ray += totalWarps) {
        // Each ray is 128 floats = 32 float4; lane l owns elements [4l, 4l+4).
        const long idx = (long)ray * 32 + lane;
        const float4 wv = __ldg(w4 + idx);
        const float4 mv = __ldg(m4 + idx);
        const float4 sv = __ldg(s4 + idx);

        // uni term: s * w^2
        float uni = sv.x * wv.x * wv.x + sv.y * wv.y * wv.y
                  + sv.z * wv.z * wv.z + sv.w * wv.w * wv.w;

        // per-lane w*m products and lane subtotals
        const float wm0 = wv.x * mv.x, wm1 = wv.y * mv.y;
        const float wm2 = wv.z * mv.z, wm3 = wv.w * mv.w;
        const float wsum  = (wv.x + wv.y) + (wv.z + wv.w);
        const float wmsum = (wm0 + wm1) + (wm2 + wm3);

        // inclusive warp scans of lane subtotals (w and w*m together)
        float wi = wsum, wmi = wmsum;
        #pragma unroll
        for (int d = 1; d < 32; d <<= 1) {
            float tw = __shfl_up_sync(0xffffffffu, wi,  d);
            float tm = __shfl_up_sync(0xffffffffu, wmi, d);
            if (lane >= d) { wi += tw; wmi += tm; }
        }
        // exclusive prefixes at this lane's first element
        float W  = wi  - wsum;
        float WM = wmi - wmsum;

        // bi term: sequential within the lane's 4 elements.
        float bi;
        bi  = wm0 * W - wv.x * WM;  W += wv.x;  WM += wm0;
        bi += wm1 * W - wv.y * WM;  W += wv.y;  WM += wm1;
        bi += wm2 * W - wv.z * WM;  W += wv.z;  WM += wm2;
        bi += wm3 * W - wv.w * WM;

        acc += (1.0f / 3.0f) * uni + 2.0f * bi;
    }

    // warp reduce
    #pragma unroll
    for (int d = 16; d; d >>= 1)
        acc += __shfl_xor_sync(0xffffffffu, acc, d);

    __shared__ float wsums[WARPS_PER_BLK];
    if (lane == 0) wsums[warpInBlk] = acc;
    __syncthreads();

    // Block partial + last-block election
    __shared__ bool isLast;
    if (threadIdx.x == 0) {
        float t = 0.0f;
        #pragma unroll
        for (int i = 0; i < WARPS_PER_BLK; i++) t += wsums[i];
        g_partials[blockIdx.x] = t;
        __threadfence();
        unsigned int old = atomicAdd(&g_count, 1u);
        isLast = (old == gridDim.x - 1);
    }
    __syncthreads();

    if (isLast) {
        __threadfence();  // acquire: make all blocks' partials visible
        double d = 0.0;
        for (int i = threadIdx.x; i < (int)gridDim.x; i += THREADS)
            d += (double)g_partials[i];

        __shared__ double sh[THREADS];
        sh[threadIdx.x] = d;
        __syncthreads();
        #pragma unroll
        for (int st = THREADS / 2; st; st >>= 1) {
            if (threadIdx.x < st) sh[threadIdx.x] += sh[threadIdx.x + st];
            __syncthreads();
        }
        if (threadIdx.x == 0) {
            out[0] = (float)(sh[0] * 0.01 / (double)B);
            g_count = 0;  // reset for next graph replay
        }
    }
}

extern "C" void kernel_launch(void* const* d_in, const int* in_sizes, int n_in,
                              void* d_out, int out_size)
{
    const float4* w4 = (const float4*)d_in[0];  // weights   [B,128]
    const float4* m4 = (const float4*)d_in[1];  // distances [B,128]
    const float4* s4 = (const float4*)d_in[2];  // intervals [B,128]
    float* out = (float*)d_out;

    const int B = in_sizes[0] / N_SAMPLES;

    distloss_fused<<<GRID_BLOCKS, THREADS>>>(w4, m4, s4, B, out);
}